// round 1
// baseline (speedup 1.0000x reference)
#include <cuda_runtime.h>
#include <math.h>

#define HKD  128
#define NKH  16
#define NVH  32
#define QKVD 8192

__device__ __forceinline__ float wredu(float v) {
#pragma unroll
    for (int o = 16; o; o >>= 1) v += __shfl_xor_sync(0xffffffffu, v, o);
    return v;
}

__global__ __launch_bounds__(128) void gdn_decode_kernel(
    const float* __restrict__ mixed_qkv,
    const float* __restrict__ bgate,
    const float* __restrict__ agate,
    const float* __restrict__ conv_state,
    const float* __restrict__ conv_w,
    const float* __restrict__ ssm,
    const float* __restrict__ alog,
    const float* __restrict__ dt_bias,
    float* __restrict__ out)
{
    const int bh = blockIdx.x;
    const int b  = bh >> 5;
    const int h  = bh & 31;
    const int hq = h >> 1;                 // GROUP = 2
    const int t    = threadIdx.x;
    const int lane = t & 31;
    const int wid  = t >> 5;

    __shared__ float k_s[HKD];
    __shared__ float q_s[HKD];
    __shared__ float v_s[HKD];
    __shared__ float red[8];
    __shared__ float red2[4];

    const float* cs = conv_state + (size_t)b * 3 * QKVD;
    const float* mq = mixed_qkv  + (size_t)b * QKVD;

    const int cq = hq * HKD + t;
    const int ck = NKH * HKD + hq * HKD + t;
    const int cv = 2 * NKH * HKD + h * HKD + t;

    // ---- causal conv (4 taps) + SiLU for this CTA's q/k/v channels ----
    float qx, kx, vx;
    {
        float4 w = *(const float4*)(conv_w + (size_t)cq * 4);
        float x  = cs[cq] * w.x + cs[QKVD + cq] * w.y + cs[2 * QKVD + cq] * w.z + mq[cq] * w.w;
        qx = x / (1.f + expf(-x));

        w = *(const float4*)(conv_w + (size_t)ck * 4);
        x = cs[ck] * w.x + cs[QKVD + ck] * w.y + cs[2 * QKVD + ck] * w.z + mq[ck] * w.w;
        kx = x / (1.f + expf(-x));

        w = *(const float4*)(conv_w + (size_t)cv * 4);
        x = cs[cv] * w.x + cs[QKVD + cv] * w.y + cs[2 * QKVD + cv] * w.z + mq[cv] * w.w;
        vx = x / (1.f + expf(-x));
    }

    // ---- block reduce: sum(q^2), sum(k^2) ----
    float pq = wredu(qx * qx);
    float pk = wredu(kx * kx);
    if (lane == 0) { red[wid] = pq; red[4 + wid] = pk; }
    __syncthreads();
    const float ssq = red[0] + red[1] + red[2] + red[3];
    const float ssk = red[4] + red[5] + red[6] + red[7];

    const float qn = qx * rsqrtf(ssq + 1e-6f) * 0.08838834764831845f; // * HK^-0.5
    const float kn = kx * rsqrtf(ssk + 1e-6f);
    q_s[t] = qn;
    k_s[t] = kn;
    v_s[t] = vx;
    __syncthreads();

    // ---- block reduce: kq = dot(kn, qn) ----
    float pkq = wredu(qn * kn);
    if (lane == 0) red2[wid] = pkq;
    __syncthreads();
    const float kq = red2[0] + red2[1] + red2[2] + red2[3];

    // ---- gating scalars (computed redundantly per thread; broadcast loads) ----
    const float aa   = agate[(size_t)b * NVH + h] + dt_bias[h];
    const float sp   = fmaxf(aa, 0.f) + log1pf(expf(-fabsf(aa)));   // softplus
    const float eg   = expf(-expf(alog[h]) * sp);                   // exp(g)
    const float bb   = bgate[(size_t)b * NVH + h];
    const float beta = 1.f / (1.f + expf(-bb));

    // ---- stream the 128x128 state tile: o = eg*(S q) + beta*(v - eg*(S k))*kq ----
    const float4* S4 = (const float4*)(ssm + (size_t)bh * HKD * HKD);
    const float4  k4 = ((const float4*)k_s)[lane];
    const float4  q4 = ((const float4*)q_s)[lane];
    float*        op = out + (size_t)bh * HKD;

    const int r0 = wid * 32;
#pragma unroll
    for (int i = 0; i < 32; i += 4) {
        const int r = r0 + i;
        float4 s0 = __ldcs(&S4[(size_t)(r + 0) * 32 + lane]);
        float4 s1 = __ldcs(&S4[(size_t)(r + 1) * 32 + lane]);
        float4 s2 = __ldcs(&S4[(size_t)(r + 2) * 32 + lane]);
        float4 s3 = __ldcs(&S4[(size_t)(r + 3) * 32 + lane]);

        float dk0 = s0.x * k4.x + s0.y * k4.y + s0.z * k4.z + s0.w * k4.w;
        float dq0 = s0.x * q4.x + s0.y * q4.y + s0.z * q4.z + s0.w * q4.w;
        float dk1 = s1.x * k4.x + s1.y * k4.y + s1.z * k4.z + s1.w * k4.w;
        float dq1 = s1.x * q4.x + s1.y * q4.y + s1.z * q4.z + s1.w * q4.w;
        float dk2 = s2.x * k4.x + s2.y * k4.y + s2.z * k4.z + s2.w * k4.w;
        float dq2 = s2.x * q4.x + s2.y * q4.y + s2.z * q4.z + s2.w * q4.w;
        float dk3 = s3.x * k4.x + s3.y * k4.y + s3.z * k4.z + s3.w * k4.w;
        float dq3 = s3.x * q4.x + s3.y * q4.y + s3.z * q4.z + s3.w * q4.w;

        dk0 = wredu(dk0); dq0 = wredu(dq0);
        dk1 = wredu(dk1); dq1 = wredu(dq1);
        dk2 = wredu(dk2); dq2 = wredu(dq2);
        dk3 = wredu(dk3); dq3 = wredu(dq3);

        if (lane == 0) {
            op[r + 0] = eg * dq0 + beta * (v_s[r + 0] - eg * dk0) * kq;
            op[r + 1] = eg * dq1 + beta * (v_s[r + 1] - eg * dk1) * kq;
            op[r + 2] = eg * dq2 + beta * (v_s[r + 2] - eg * dk2) * kq;
            op[r + 3] = eg * dq3 + beta * (v_s[r + 3] - eg * dk3) * kq;
        }
    }
}

extern "C" void kernel_launch(void* const* d_in, const int* in_sizes, int n_in,
                              void* d_out, int out_size)
{
    const float* mixed_qkv  = (const float*)d_in[0];
    const float* bgate      = (const float*)d_in[1];
    const float* agate      = (const float*)d_in[2];
    const float* conv_state = (const float*)d_in[3];
    const float* conv_w     = (const float*)d_in[4];
    const float* ssm        = (const float*)d_in[5];
    const float* alog       = (const float*)d_in[6];
    const float* dt_bias    = (const float*)d_in[7];
    float* out = (float*)d_out;

    const int B = in_sizes[0] / QKVD;
    gdn_decode_kernel<<<B * NVH, 128>>>(mixed_qkv, bgate, agate, conv_state,
                                        conv_w, ssm, alog, dt_bias, out);
}

// round 2
// speedup vs baseline: 1.0709x; 1.0709x over previous
#include <cuda_runtime.h>
#include <math.h>

#define HKD  128
#define NKH  16
#define NVH  32
#define QKVD 8192

__device__ __forceinline__ float wredu(float v) {
#pragma unroll
    for (int o = 16; o; o >>= 1) v += __shfl_xor_sync(0xffffffffu, v, o);
    return v;
}

__device__ __forceinline__ float dot4(float4 a, float4 b) {
    return a.x * b.x + a.y * b.y + a.z * b.z + a.w * b.w;
}

__global__ __launch_bounds__(128) void gdn_decode_kernel(
    const float* __restrict__ mixed_qkv,
    const float* __restrict__ bgate,
    const float* __restrict__ agate,
    const float* __restrict__ conv_state,
    const float* __restrict__ conv_w,
    const float* __restrict__ ssm,
    const float* __restrict__ alog,
    const float* __restrict__ dt_bias,
    float* __restrict__ out)
{
    const int bh = blockIdx.x;
    const int b  = bh >> 5;
    const int h  = bh & 31;
    const int hq = h >> 1;                 // GROUP = 2
    const int t    = threadIdx.x;
    const int lane = t & 31;
    const int wid  = t >> 5;

    __shared__ __align__(16) float q_s[HKD];
    __shared__ __align__(16) float k_s[HKD];
    __shared__ __align__(16) float v_s[HKD];
    __shared__ float red[12];

    // ---- prefetch batch 0 of state rows BEFORE any prologue work ----
    const float4* Sb = (const float4*)(ssm + (size_t)bh * HKD * HKD)
                       + (size_t)wid * 32 * 32 + lane;
    float4 c0 = __ldcs(Sb + 0 * 32);
    float4 c1 = __ldcs(Sb + 1 * 32);
    float4 c2 = __ldcs(Sb + 2 * 32);
    float4 c3 = __ldcs(Sb + 3 * 32);

    // ---- causal conv (4 taps) + SiLU for this CTA's q/k/v channels ----
    const float* cs = conv_state + (size_t)b * 3 * QKVD;
    const float* mq = mixed_qkv  + (size_t)b * QKVD;
    const int cq = hq * HKD + t;
    const int ck = NKH * HKD + hq * HKD + t;
    const int cv = 2 * NKH * HKD + h * HKD + t;

    float qx, kx, vx;
    {
        float4 w = *(const float4*)(conv_w + (size_t)cq * 4);
        float x  = cs[cq] * w.x + cs[QKVD + cq] * w.y + cs[2 * QKVD + cq] * w.z + mq[cq] * w.w;
        qx = x / (1.f + expf(-x));

        w = *(const float4*)(conv_w + (size_t)ck * 4);
        x = cs[ck] * w.x + cs[QKVD + ck] * w.y + cs[2 * QKVD + ck] * w.z + mq[ck] * w.w;
        kx = x / (1.f + expf(-x));

        w = *(const float4*)(conv_w + (size_t)cv * 4);
        x = cs[cv] * w.x + cs[QKVD + cv] * w.y + cs[2 * QKVD + cv] * w.z + mq[cv] * w.w;
        vx = x / (1.f + expf(-x));
    }

    // raw values to shared, single fused reduction (q^2, k^2, q.k)
    q_s[t] = qx;
    k_s[t] = kx;
    v_s[t] = vx;
    float pq = wredu(qx * qx);
    float pk = wredu(kx * kx);
    float pc = wredu(qx * kx);
    if (lane == 0) { red[wid] = pq; red[4 + wid] = pk; red[8 + wid] = pc; }

    // ---- gating scalars (independent of the reduction; hides sync) ----
    const float aa   = agate[(size_t)b * NVH + h] + dt_bias[h];
    const float sp   = fmaxf(aa, 0.f) + log1pf(expf(-fabsf(aa)));   // softplus
    const float eg   = expf(-expf(alog[h]) * sp);                   // exp(g)
    const float beta = 1.f / (1.f + expf(-bgate[(size_t)b * NVH + h]));

    __syncthreads();   // the only barrier

    const float rq = rsqrtf(red[0] + red[1] + red[2] + red[3] + 1e-6f)
                     * 0.08838834764831845f;                        // * HK^-0.5
    const float rk = rsqrtf(red[4] + red[5] + red[6] + red[7] + 1e-6f);
    const float kq = (red[8] + red[9] + red[10] + red[11]) * rq * rk;

    float4 q4 = ((const float4*)q_s)[lane];
    q4.x *= rq; q4.y *= rq; q4.z *= rq; q4.w *= rq;
    float4 k4 = ((const float4*)k_s)[lane];
    k4.x *= rk; k4.y *= rk; k4.z *= rk; k4.w *= rk;

    float*       op = out + (size_t)bh * HKD + wid * 32;
    const float* vr = v_s + wid * 32;

    // ---- 8 batches of 4 rows, double-buffered: next loads issue before
    //      the current batch's shuffle-reduction chains ----
#pragma unroll
    for (int j = 0; j < 8; j++) {
        float4 n0, n1, n2, n3;
        if (j < 7) {
            n0 = __ldcs(Sb + ((j + 1) * 4 + 0) * 32);
            n1 = __ldcs(Sb + ((j + 1) * 4 + 1) * 32);
            n2 = __ldcs(Sb + ((j + 1) * 4 + 2) * 32);
            n3 = __ldcs(Sb + ((j + 1) * 4 + 3) * 32);
        }

        float dk0 = dot4(c0, k4), dq0 = dot4(c0, q4);
        float dk1 = dot4(c1, k4), dq1 = dot4(c1, q4);
        float dk2 = dot4(c2, k4), dq2 = dot4(c2, q4);
        float dk3 = dot4(c3, k4), dq3 = dot4(c3, q4);

        dk0 = wredu(dk0); dq0 = wredu(dq0);
        dk1 = wredu(dk1); dq1 = wredu(dq1);
        dk2 = wredu(dk2); dq2 = wredu(dq2);
        dk3 = wredu(dk3); dq3 = wredu(dq3);

        if (lane == 0) {
            const int r = j * 4;
            op[r + 0] = eg * dq0 + beta * (vr[r + 0] - eg * dk0) * kq;
            op[r + 1] = eg * dq1 + beta * (vr[r + 1] - eg * dk1) * kq;
            op[r + 2] = eg * dq2 + beta * (vr[r + 2] - eg * dk2) * kq;
            op[r + 3] = eg * dq3 + beta * (vr[r + 3] - eg * dk3) * kq;
        }

        c0 = n0; c1 = n1; c2 = n2; c3 = n3;
    }
}

extern "C" void kernel_launch(void* const* d_in, const int* in_sizes, int n_in,
                              void* d_out, int out_size)
{
    const float* mixed_qkv  = (const float*)d_in[0];
    const float* bgate      = (const float*)d_in[1];
    const float* agate      = (const float*)d_in[2];
    const float* conv_state = (const float*)d_in[3];
    const float* conv_w     = (const float*)d_in[4];
    const float* ssm        = (const float*)d_in[5];
    const float* alog       = (const float*)d_in[6];
    const float* dt_bias    = (const float*)d_in[7];
    float* out = (float*)d_out;

    const int B = in_sizes[0] / QKVD;
    gdn_decode_kernel<<<B * NVH, 128>>>(mixed_qkv, bgate, agate, conv_state,
                                        conv_w, ssm, alog, dt_bias, out);
}